// round 2
// baseline (speedup 1.0000x reference)
#include <cuda_runtime.h>

// LaneAttention fused kernel, fp32, sm_103a.
// One block per (b,v) unit. 512 threads. All intermediates in SMEM.

#define TT   30     // len_pred
#define BB   64     // batch
#define VVN  32     // n_vehicles
#define FF   128    // feature size
#define LL   64     // n_lanes
#define LFN  64     // lane feature size
#define NH   4      // heads
#define HD   32     // head dim
#define THN  20     // len_hist
#define NBLK (BB*VVN)   // 2048
#define NTHR 512

#define KV_STRIDE 132   // padded row stride for sK/sV (float4-aligned, reduces conflicts)
#define WT_STRIDE 132   // padded row stride for transposed weight tile

// SMEM layout (in floats)
#define SK_OFF    0
#define SV_OFF    (SK_OFF  + LL*KV_STRIDE)        // 8448
#define SWT_OFF   (SV_OFF  + LL*KV_STRIDE)        // 16896
#define SX_OFF    (SWT_OFF + 64*WT_STRIDE)        // 25344
#define SQ_OFF    (SX_OFF  + TT*FF)               // 29184
#define SLO_OFF   (SQ_OFF  + TT*FF)               // 33024  (lanes 64x64, reused as attn-out 30x128)
#define SMASK_OFF (SLO_OFF + LL*LFN)              // 37120
#define SMEM_FLOATS (SMASK_OFF + LL)              // 37184  -> 148736 bytes

__global__ void __launch_bounds__(NTHR, 1)
lane_attn_kernel(const float* __restrict__ veh,
                 const float* __restrict__ lanes,
                 const int* __restrict__ maskl,
                 const float* __restrict__ Wk, const float* __restrict__ Wv,
                 const float* __restrict__ Wq, const float* __restrict__ Wc,
                 float* __restrict__ out)
{
    extern __shared__ float sm[];
    float* sK    = sm + SK_OFF;
    float* sV    = sm + SV_OFF;
    float* sWt   = sm + SWT_OFF;   // transposed weight tile [f][g], also reused as sP
    float* sX    = sm + SX_OFF;    // vehicles rows [t][f]
    float* sQ    = sm + SQ_OFF;    // q [t][f]
    float* sLO   = sm + SLO_OFF;   // lanes [l][lf], later attn output [t][f]
    float* sMask = sm + SMASK_OFF; // 1.0 = keep, 0.0 = masked
    float* sP    = sWt;            // probabilities [t][h*64+l], reuses weight buffer

    const int tid  = threadIdx.x;
    const int w    = tid >> 5;
    const int lane = tid & 31;
    const int bid  = blockIdx.x;

    // ---------------- Phase 1: loads ----------------
    {
        const float* lp = lanes + (size_t)bid * (LL * LFN);
        for (int idx = tid; idx < LL * LFN; idx += NTHR) sLO[idx] = lp[idx];

        for (int idx = tid; idx < TT * FF; idx += NTHR) {
            int t = idx >> 7, f = idx & 127;
            sX[idx] = veh[(size_t)(t * NBLK + bid) * FF + f];
        }
        if (tid < LL) {
            int m = 0;
            #pragma unroll
            for (int th = 0; th < THN; th++)
                m |= maskl[(size_t)(th * NBLK + bid) * LL + tid];
            sMask[tid] = m ? 1.0f : 0.0f;
        }
        for (int idx = tid; idx < FF * LFN; idx += NTHR) {
            int g = idx >> 6, f = idx & 63;
            sWt[f * WT_STRIDE + g] = Wk[idx];
        }
    }
    __syncthreads();

    // ---------------- Phase 2a: K = lanes @ Wk^T ----------------
    // warp w owns rows l = 4w..4w+3, lane owns g = 4*lane..4*lane+3
    {
        float acc[4][4];
        #pragma unroll
        for (int i = 0; i < 4; i++) { acc[i][0]=acc[i][1]=acc[i][2]=acc[i][3]=0.f; }
        const int l0 = w * 4;
        #pragma unroll 4
        for (int f = 0; f < LFN; f++) {
            float4 wv = *(const float4*)(sWt + f * WT_STRIDE + 4 * lane);
            #pragma unroll
            for (int il = 0; il < 4; il++) {
                float a = sLO[(l0 + il) * LFN + f];
                acc[il][0] = fmaf(a, wv.x, acc[il][0]);
                acc[il][1] = fmaf(a, wv.y, acc[il][1]);
                acc[il][2] = fmaf(a, wv.z, acc[il][2]);
                acc[il][3] = fmaf(a, wv.w, acc[il][3]);
            }
        }
        #pragma unroll
        for (int il = 0; il < 4; il++) {
            *(float4*)(sK + (l0 + il) * KV_STRIDE + 4 * lane) =
                make_float4(acc[il][0], acc[il][1], acc[il][2], acc[il][3]);
        }
    }
    __syncthreads();

    // load Wv^T
    for (int idx = tid; idx < FF * LFN; idx += NTHR) {
        int g = idx >> 6, f = idx & 63;
        sWt[f * WT_STRIDE + g] = Wv[idx];
    }
    __syncthreads();

    // ---------------- Phase 2b: V = lanes @ Wv^T ----------------
    {
        float acc[4][4];
        #pragma unroll
        for (int i = 0; i < 4; i++) { acc[i][0]=acc[i][1]=acc[i][2]=acc[i][3]=0.f; }
        const int l0 = w * 4;
        #pragma unroll 4
        for (int f = 0; f < LFN; f++) {
            float4 wv = *(const float4*)(sWt + f * WT_STRIDE + 4 * lane);
            #pragma unroll
            for (int il = 0; il < 4; il++) {
                float a = sLO[(l0 + il) * LFN + f];
                acc[il][0] = fmaf(a, wv.x, acc[il][0]);
                acc[il][1] = fmaf(a, wv.y, acc[il][1]);
                acc[il][2] = fmaf(a, wv.z, acc[il][2]);
                acc[il][3] = fmaf(a, wv.w, acc[il][3]);
            }
        }
        #pragma unroll
        for (int il = 0; il < 4; il++) {
            *(float4*)(sV + (l0 + il) * KV_STRIDE + 4 * lane) =
                make_float4(acc[il][0], acc[il][1], acc[il][2], acc[il][3]);
        }
    }
    __syncthreads();

    // ---------------- Phase 3: Q = X @ Wq^T (two 64-wide f-halves) ----------------
    {
        float qacc[2][4];
        qacc[0][0]=qacc[0][1]=qacc[0][2]=qacc[0][3]=0.f;
        qacc[1][0]=qacc[1][1]=qacc[1][2]=qacc[1][3]=0.f;
        for (int half = 0; half < 2; half++) {
            for (int idx = tid; idx < FF * 64; idx += NTHR) {
                int g = idx >> 6, f = idx & 63;
                sWt[f * WT_STRIDE + g] = Wq[g * FF + half * 64 + f];
            }
            __syncthreads();
            #pragma unroll 2
            for (int f = 0; f < 64; f++) {
                float4 wv = *(const float4*)(sWt + f * WT_STRIDE + 4 * lane);
                #pragma unroll
                for (int jt = 0; jt < 2; jt++) {
                    int t = w + 16 * jt;
                    float a = (t < TT) ? sX[t * FF + half * 64 + f] : 0.f;
                    qacc[jt][0] = fmaf(a, wv.x, qacc[jt][0]);
                    qacc[jt][1] = fmaf(a, wv.y, qacc[jt][1]);
                    qacc[jt][2] = fmaf(a, wv.z, qacc[jt][2]);
                    qacc[jt][3] = fmaf(a, wv.w, qacc[jt][3]);
                }
            }
            __syncthreads();
        }
        #pragma unroll
        for (int jt = 0; jt < 2; jt++) {
            int t = w + 16 * jt;
            if (t < TT)
                *(float4*)(sQ + t * FF + 4 * lane) =
                    make_float4(qacc[jt][0], qacc[jt][1], qacc[jt][2], qacc[jt][3]);
        }
    }
    __syncthreads();

    // ---------------- Phase 4a: scores + softmax -> sP ----------------
    // warp = (head h = w&3, t-chunk c = w>>2 of 8 timesteps)
    {
        const int h  = w & 3;
        const int c  = w >> 2;
        const int t0 = c * 8;
        const int gb = h * HD;
        float sc0[8], sc1[8];
        #pragma unroll
        for (int j = 0; j < 8; j++) { sc0[j] = 0.f; sc1[j] = 0.f; }

        #pragma unroll 4
        for (int d = 0; d < HD; d++) {
            float k0 = sK[lane        * KV_STRIDE + gb + d];
            float k1 = sK[(lane + 32) * KV_STRIDE + gb + d];
            #pragma unroll
            for (int j = 0; j < 8; j++) {
                int tj = t0 + j; tj = tj < TT ? tj : (TT - 1);
                float qd = sQ[tj * FF + gb + d];
                sc0[j] = fmaf(qd, k0, sc0[j]);
                sc1[j] = fmaf(qd, k1, sc1[j]);
            }
        }
        const float scale = 0.17677669529663687f; // 1/sqrt(32)
        const float f0 = sMask[lane];
        const float f1 = sMask[lane + 32];
        #pragma unroll
        for (int j = 0; j < 8; j++) {
            if (t0 + j >= TT) break;
            float s0 = (f0 > 0.f) ? sc0[j] * scale : -1e9f;
            float s1 = (f1 > 0.f) ? sc1[j] * scale : -1e9f;
            float m = fmaxf(s0, s1);
            #pragma unroll
            for (int o = 16; o; o >>= 1) m = fmaxf(m, __shfl_xor_sync(0xffffffffu, m, o));
            float e0 = __expf(s0 - m), e1 = __expf(s1 - m);
            float ss = e0 + e1;
            #pragma unroll
            for (int o = 16; o; o >>= 1) ss += __shfl_xor_sync(0xffffffffu, ss, o);
            float inv = 1.0f / ss;
            sP[(t0 + j) * (NH * LL) + h * LL + lane]      = e0 * inv;
            sP[(t0 + j) * (NH * LL) + h * LL + lane + 32] = e1 * inv;
        }
    }
    __syncthreads();

    // ---------------- Phase 4b: O = P @ V -> sLO ----------------
    {
        const int h  = w & 3;
        const int c  = w >> 2;
        const int t0 = c * 8;
        const int gb = h * HD;
        const int cnt = (TT - t0) < 8 ? (TT - t0) : 8;
        float oacc[8];
        #pragma unroll
        for (int j = 0; j < 8; j++) oacc[j] = 0.f;
        #pragma unroll 2
        for (int l = 0; l < LL; l++) {
            float vv = sV[l * KV_STRIDE + gb + lane];
            #pragma unroll
            for (int j = 0; j < 8; j++) {
                int tj = t0 + j; tj = tj < TT ? tj : (TT - 1);
                oacc[j] = fmaf(sP[tj * (NH * LL) + h * LL + l], vv, oacc[j]);
            }
        }
        for (int j = 0; j < cnt; j++)
            sLO[(t0 + j) * FF + gb + lane] = oacc[j];
    }
    __syncthreads();

    // ---------------- Phase 5: Y = O @ Wc^T + X, write global ----------------
    {
        float yacc[2][4];
        yacc[0][0]=yacc[0][1]=yacc[0][2]=yacc[0][3]=0.f;
        yacc[1][0]=yacc[1][1]=yacc[1][2]=yacc[1][3]=0.f;
        for (int half = 0; half < 2; half++) {
            for (int idx = tid; idx < FF * 64; idx += NTHR) {
                int g = idx >> 6, f = idx & 63;
                sWt[f * WT_STRIDE + g] = Wc[g * FF + half * 64 + f];
            }
            __syncthreads();
            #pragma unroll 2
            for (int f = 0; f < 64; f++) {
                float4 wv = *(const float4*)(sWt + f * WT_STRIDE + 4 * lane);
                #pragma unroll
                for (int jt = 0; jt < 2; jt++) {
                    int t = w + 16 * jt;
                    float a = (t < TT) ? sLO[t * FF + half * 64 + f] : 0.f;
                    yacc[jt][0] = fmaf(a, wv.x, yacc[jt][0]);
                    yacc[jt][1] = fmaf(a, wv.y, yacc[jt][1]);
                    yacc[jt][2] = fmaf(a, wv.z, yacc[jt][2]);
                    yacc[jt][3] = fmaf(a, wv.w, yacc[jt][3]);
                }
            }
            __syncthreads();
        }
        #pragma unroll
        for (int jt = 0; jt < 2; jt++) {
            int t = w + 16 * jt;
            if (t < TT) {
                float4 xv = *(const float4*)(sX + t * FF + 4 * lane);
                float4 yv = make_float4(yacc[jt][0] + xv.x, yacc[jt][1] + xv.y,
                                        yacc[jt][2] + xv.z, yacc[jt][3] + xv.w);
                *(float4*)(out + (size_t)(t * NBLK + bid) * FF + 4 * lane) = yv;
            }
        }
    }
}

extern "C" void kernel_launch(void* const* d_in, const int* in_sizes, int n_in,
                              void* d_out, int out_size)
{
    const float* veh   = (const float*)d_in[0];
    const float* lanes = (const float*)d_in[1];
    const int*   maskl = (const int*)d_in[2];
    const float* Wk    = (const float*)d_in[3];
    const float* Wv    = (const float*)d_in[4];
    const float* Wq    = (const float*)d_in[5];
    const float* Wc    = (const float*)d_in[6];

    const size_t smem = SMEM_FLOATS * sizeof(float);
    cudaFuncSetAttribute(lane_attn_kernel,
                         cudaFuncAttributeMaxDynamicSharedMemorySize, (int)smem);
    lane_attn_kernel<<<NBLK, NTHR, smem>>>(veh, lanes, maskl, Wk, Wv, Wq, Wc,
                                           (float*)d_out);
}

// round 3
// speedup vs baseline: 1.3063x; 1.3063x over previous
#include <cuda_runtime.h>

// LaneAttention fused, fp32, sm_103a. 2 CTAs/SM target.
// One block per (b,v). 512 threads. Lane owns g = lane+32k (conflict-free
// scalar weight reads + transposed-K stores). t processed in halves of 16.

#define TT   30
#define FF   128
#define LL   64
#define LFN  64
#define NH   4
#define HD   32
#define THN  20
#define NBLK 2048
#define NTHR 512

// SMEM regions (float offsets)
#define KT_OFF 0          // Kt[128][65]  (g-major, stride 65)
#define W_OFF  8320       // sW[128][65]  (g-major, stride 65); sP overlays
#define P_OFF  8320       // sP[16][256]  (tl, h*64+l)
#define V_OFF  16640      // sV[64][128]  (l-major)
#define X_OFF  24832      // sX[16][128]; sO overlays; lanes[64][64] overlays X+Q
#define O_OFF  24832
#define LN_OFF 24832
#define Q_OFF  26880      // sQ[16][128]
#define SMEM_FLOATS 28928 // 115712 bytes

__device__ __forceinline__ void load_w_tile(float* sm, const float* Wsrc,
                                            int foff, int ldw, int tid)
{
    // sW[g][f] natural layout, stride 65; coalesced LDG + conflict-free STS
    for (int idx = tid; idx < 128 * 64; idx += NTHR) {
        int g = idx >> 6, f = idx & 63;
        sm[W_OFF + g * 65 + f] = Wsrc[g * ldw + foff + f];
    }
}

__global__ void __launch_bounds__(NTHR, 2)
lane_attn_kernel(const float* __restrict__ veh,
                 const float* __restrict__ lanes,
                 const int* __restrict__ maskl,
                 const float* __restrict__ Wk, const float* __restrict__ Wv,
                 const float* __restrict__ Wq, const float* __restrict__ Wc,
                 float* __restrict__ out)
{
    extern __shared__ float sm[];
    const int tid  = threadIdx.x;
    const int w    = tid >> 5;
    const int lane = tid & 31;
    const int bid  = blockIdx.x;

    // ---------- mask (kept in registers; every thread computes its 2 lanes) ----------
    int mi0 = 0, mi1 = 0;
    #pragma unroll
    for (int th = 0; th < THN; th++) {
        const int* mp = maskl + (size_t)(th * NBLK + bid) * LL;
        mi0 |= mp[lane];
        mi1 |= mp[lane + 32];
    }
    const bool km0 = (mi0 != 0), km1 = (mi1 != 0);

    // ---------- load lanes + Wk ----------
    {
        const float* lp = lanes + (size_t)bid * (LL * LFN);
        for (int idx = tid; idx < LL * LFN; idx += NTHR) sm[LN_OFF + idx] = lp[idx];
        load_w_tile(sm, Wk, 0, 64, tid);
    }
    __syncthreads();

    // ---------- K phase: Kt[g][l] = (lanes @ Wk^T)^T ----------
    {
        const int l0 = w * 4;
        float acc[4][4];
        #pragma unroll
        for (int i = 0; i < 4; i++) { acc[i][0]=acc[i][1]=acc[i][2]=acc[i][3]=0.f; }
        #pragma unroll 2
        for (int f = 0; f < LFN; f += 4) {
            float4 a0 = *(const float4*)&sm[LN_OFF + (l0+0)*64 + f];
            float4 a1 = *(const float4*)&sm[LN_OFF + (l0+1)*64 + f];
            float4 a2 = *(const float4*)&sm[LN_OFF + (l0+2)*64 + f];
            float4 a3 = *(const float4*)&sm[LN_OFF + (l0+3)*64 + f];
            #pragma unroll
            for (int k = 0; k < 4; k++) {
                const float* wp = &sm[W_OFF + (lane + 32*k) * 65 + f];
                float w0 = wp[0], w1 = wp[1], w2 = wp[2], w3 = wp[3];
                acc[0][k] = fmaf(a0.x,w0, fmaf(a0.y,w1, fmaf(a0.z,w2, fmaf(a0.w,w3, acc[0][k]))));
                acc[1][k] = fmaf(a1.x,w0, fmaf(a1.y,w1, fmaf(a1.z,w2, fmaf(a1.w,w3, acc[1][k]))));
                acc[2][k] = fmaf(a2.x,w0, fmaf(a2.y,w1, fmaf(a2.z,w2, fmaf(a2.w,w3, acc[2][k]))));
                acc[3][k] = fmaf(a3.x,w0, fmaf(a3.y,w1, fmaf(a3.z,w2, fmaf(a3.w,w3, acc[3][k]))));
            }
        }
        #pragma unroll
        for (int k = 0; k < 4; k++)
            #pragma unroll
            for (int il = 0; il < 4; il++)
                sm[KT_OFF + (lane + 32*k) * 65 + (l0 + il)] = acc[il][k];
    }
    __syncthreads();
    load_w_tile(sm, Wv, 0, 64, tid);
    __syncthreads();

    // ---------- V phase: sV[l][g] ----------
    {
        const int l0 = w * 4;
        float acc[4][4];
        #pragma unroll
        for (int i = 0; i < 4; i++) { acc[i][0]=acc[i][1]=acc[i][2]=acc[i][3]=0.f; }
        #pragma unroll 2
        for (int f = 0; f < LFN; f += 4) {
            float4 a0 = *(const float4*)&sm[LN_OFF + (l0+0)*64 + f];
            float4 a1 = *(const float4*)&sm[LN_OFF + (l0+1)*64 + f];
            float4 a2 = *(const float4*)&sm[LN_OFF + (l0+2)*64 + f];
            float4 a3 = *(const float4*)&sm[LN_OFF + (l0+3)*64 + f];
            #pragma unroll
            for (int k = 0; k < 4; k++) {
                const float* wp = &sm[W_OFF + (lane + 32*k) * 65 + f];
                float w0 = wp[0], w1 = wp[1], w2 = wp[2], w3 = wp[3];
                acc[0][k] = fmaf(a0.x,w0, fmaf(a0.y,w1, fmaf(a0.z,w2, fmaf(a0.w,w3, acc[0][k]))));
                acc[1][k] = fmaf(a1.x,w0, fmaf(a1.y,w1, fmaf(a1.z,w2, fmaf(a1.w,w3, acc[1][k]))));
                acc[2][k] = fmaf(a2.x,w0, fmaf(a2.y,w1, fmaf(a2.z,w2, fmaf(a2.w,w3, acc[2][k]))));
                acc[3][k] = fmaf(a3.x,w0, fmaf(a3.y,w1, fmaf(a3.z,w2, fmaf(a3.w,w3, acc[3][k]))));
            }
        }
        #pragma unroll
        for (int k = 0; k < 4; k++)
            #pragma unroll
            for (int il = 0; il < 4; il++)
                sm[V_OFF + (l0 + il) * FF + (lane + 32*k)] = acc[il][k];
    }
    __syncthreads();

    // ---------- per-t-half pipeline ----------
    for (int th2 = 0; th2 < 2; th2++) {
        const int tbase = th2 * 16;
        const int tcnt  = (TT - tbase) < 16 ? (TT - tbase) : 16;

        // load X half (overwrites lanes / previous O) + Wq half0
        for (int idx = tid; idx < tcnt * FF; idx += NTHR) {
            int tl = idx >> 7, f = idx & 127;
            sm[X_OFF + idx] = veh[(size_t)((tbase + tl) * NBLK + bid) * FF + f];
        }
        load_w_tile(sm, Wq, 0, FF, tid);
        __syncthreads();

        // -------- Q: warp = (tq = w>>2, gq = w&3); 4 t x 1 g per lane --------
        {
            const int tq = w >> 2, gq = w & 3;
            const int g  = lane + 32 * gq;
            float acc[4] = {0.f, 0.f, 0.f, 0.f};
            #pragma unroll
            for (int half = 0; half < 2; half++) {
                #pragma unroll 2
                for (int f = 0; f < 64; f += 4) {
                    const float* wp = &sm[W_OFF + g * 65 + f];
                    float w0 = wp[0], w1 = wp[1], w2 = wp[2], w3 = wp[3];
                    #pragma unroll
                    for (int it = 0; it < 4; it++) {
                        float4 a = *(const float4*)&sm[X_OFF + (tq*4+it)*FF + half*64 + f];
                        acc[it] = fmaf(a.x,w0, fmaf(a.y,w1, fmaf(a.z,w2, fmaf(a.w,w3, acc[it]))));
                    }
                }
                if (half == 0) {
                    __syncthreads();
                    load_w_tile(sm, Wq, 64, FF, tid);
                    __syncthreads();
                }
            }
            #pragma unroll
            for (int it = 0; it < 4; it++)
                if (tq*4 + it < tcnt)
                    sm[Q_OFF + (tq*4+it)*FF + g] = acc[it];
        }
        __syncthreads();

        // -------- scores + softmax: warp = (h = w&3, tc = w>>2); 4 t each --------
        {
            const int h  = w & 3;
            const int tc = w >> 2;
            const int gb = h * HD;
            float sc0[4] = {0,0,0,0}, sc1[4] = {0,0,0,0};
            #pragma unroll 2
            for (int d = 0; d < HD; d += 4) {
                float k00 = sm[KT_OFF + (gb+d+0)*65 + lane];
                float k01 = sm[KT_OFF + (gb+d+1)*65 + lane];
                float k02 = sm[KT_OFF + (gb+d+2)*65 + lane];
                float k03 = sm[KT_OFF + (gb+d+3)*65 + lane];
                float k10 = sm[KT_OFF + (gb+d+0)*65 + lane + 32];
                float k11 = sm[KT_OFF + (gb+d+1)*65 + lane + 32];
                float k12 = sm[KT_OFF + (gb+d+2)*65 + lane + 32];
                float k13 = sm[KT_OFF + (gb+d+3)*65 + lane + 32];
                #pragma unroll
                for (int it = 0; it < 4; it++) {
                    float4 q = *(const float4*)&sm[Q_OFF + (tc*4+it)*FF + gb + d];
                    sc0[it] = fmaf(q.x,k00, fmaf(q.y,k01, fmaf(q.z,k02, fmaf(q.w,k03, sc0[it]))));
                    sc1[it] = fmaf(q.x,k10, fmaf(q.y,k11, fmaf(q.z,k12, fmaf(q.w,k13, sc1[it]))));
                }
            }
            const float scale = 0.17677669529663687f; // 1/sqrt(32)
            #pragma unroll
            for (int it = 0; it < 4; it++) {
                int tl = tc*4 + it;
                if (tl >= tcnt) break;
                float s0 = km0 ? sc0[it] * scale : -1e9f;
                float s1 = km1 ? sc1[it] * scale : -1e9f;
                float m = fmaxf(s0, s1);
                #pragma unroll
                for (int o = 16; o; o >>= 1) m = fmaxf(m, __shfl_xor_sync(0xffffffffu, m, o));
                float e0 = __expf(s0 - m), e1 = __expf(s1 - m);
                float ss = e0 + e1;
                #pragma unroll
                for (int o = 16; o; o >>= 1) ss += __shfl_xor_sync(0xffffffffu, ss, o);
                float inv = 1.0f / ss;
                sm[P_OFF + tl*256 + h*64 + lane]      = e0 * inv;
                sm[P_OFF + tl*256 + h*64 + lane + 32] = e1 * inv;
            }
        }
        __syncthreads();

        // -------- O = P @ V : warp = (h, tc); out d = lane --------
        {
            const int h  = w & 3;
            const int tc = w >> 2;
            const int gb = h * HD;
            float oacc[4] = {0,0,0,0};
            #pragma unroll 2
            for (int l = 0; l < LL; l += 4) {
                float v0 = sm[V_OFF + (l+0)*FF + gb + lane];
                float v1 = sm[V_OFF + (l+1)*FF + gb + lane];
                float v2 = sm[V_OFF + (l+2)*FF + gb + lane];
                float v3 = sm[V_OFF + (l+3)*FF + gb + lane];
                #pragma unroll
                for (int it = 0; it < 4; it++) {
                    float4 p = *(const float4*)&sm[P_OFF + (tc*4+it)*256 + h*64 + l];
                    oacc[it] = fmaf(p.x,v0, fmaf(p.y,v1, fmaf(p.z,v2, fmaf(p.w,v3, oacc[it]))));
                }
            }
            #pragma unroll
            for (int it = 0; it < 4; it++)
                if (tc*4 + it < tcnt)
                    sm[O_OFF + (tc*4+it)*FF + gb + lane] = oacc[it];
        }
        __syncthreads();

        // -------- Y = O @ Wc^T + X(residual from global) --------
        load_w_tile(sm, Wc, 0, FF, tid);
        __syncthreads();
        {
            const int tq = w >> 2, gq = w & 3;
            const int g  = lane + 32 * gq;
            // prefetch residuals
            float xv[4];
            #pragma unroll
            for (int it = 0; it < 4; it++) {
                int tl = tq*4 + it;
                xv[it] = (tl < tcnt)
                    ? veh[(size_t)((tbase + tl) * NBLK + bid) * FF + g] : 0.f;
            }
            float acc[4] = {0.f, 0.f, 0.f, 0.f};
            #pragma unroll
            for (int half = 0; half < 2; half++) {
                #pragma unroll 2
                for (int f = 0; f < 64; f += 4) {
                    const float* wp = &sm[W_OFF + g * 65 + f];
                    float w0 = wp[0], w1 = wp[1], w2 = wp[2], w3 = wp[3];
                    #pragma unroll
                    for (int it = 0; it < 4; it++) {
                        float4 a = *(const float4*)&sm[O_OFF + (tq*4+it)*FF + half*64 + f];
                        acc[it] = fmaf(a.x,w0, fmaf(a.y,w1, fmaf(a.z,w2, fmaf(a.w,w3, acc[it]))));
                    }
                }
                if (half == 0) {
                    __syncthreads();
                    load_w_tile(sm, Wc, 64, FF, tid);
                    __syncthreads();
                }
            }
            #pragma unroll
            for (int it = 0; it < 4; it++) {
                int tl = tq*4 + it;
                if (tl < tcnt)
                    out[(size_t)((tbase + tl) * NBLK + bid) * FF + g] = acc[it] + xv[it];
            }
        }
        __syncthreads();
    }
}

extern "C" void kernel_launch(void* const* d_in, const int* in_sizes, int n_in,
                              void* d_out, int out_size)
{
    const float* veh   = (const float*)d_in[0];
    const float* lanes = (const float*)d_in[1];
    const int*   maskl = (const int*)d_in[2];
    const float* Wk    = (const float*)d_in[3];
    const float* Wv    = (const float*)d_in[4];
    const float* Wq    = (const float*)d_in[5];
    const float* Wc    = (const float*)d_in[6];

    const size_t smem = SMEM_FLOATS * sizeof(float); // 115712 B
    cudaFuncSetAttribute(lane_attn_kernel,
                         cudaFuncAttributeMaxDynamicSharedMemorySize, (int)smem);
    lane_attn_kernel<<<NBLK, NTHR, smem>>>(veh, lanes, maskl, Wk, Wv, Wq, Wc,
                                           (float*)d_out);
}